// round 12
// baseline (speedup 1.0000x reference)
#include <cuda_runtime.h>

#define TILES 800
#define NTHR  256
#define CHUNKS 16

__device__ float g_z[2 * 400 * 40 * 64];
__device__ float g_cf[2 * 16 * 40 * 64];
// bf16-split B staging: [16 ch][2 split][80 n][40 (32 k + 8 pad)] bf16 = 12800 B/chunk
__device__ __align__(16) unsigned short g_bmb[16 * 6400];
__device__ __align__(16) float2 g_ct[64 * 64];

__constant__ unsigned PAIR_TBL[32] = {
  0x0100,0x0200,0x0300,0x0400,0x0500,0x0600,0x0700,
  0x0201,0x0301,0x0401,0x0501,0x0601,0x0701,
  0x0302,0x0402,0x0502,0x0602,0x0702,
  0x0403,0x0503,0x0603,0x0703,
  0x0504,0x0604,0x0704,
  0x0605,0x0705,
  0x0706,
  0x10100,0x10302,0x10504,0x10706
};

// smem (68960 B -> 3 CTAs/SM):
// gs 33088 @0          (epi: stg f32[64][82]=20992 @0, then ct f2[64][64]=32768 @0)
// A single buf 10240 @33088 (hi u@0 v@2560, lo u@5120 v@7680; row stride 80B)
// B dbuf 2x12800 @43328
// mbars @68928: mb_x, mbB0, mbB1
// prologue overlay: brs f32[4096]@33088, bis f32[4096]@49472
// epilogue overlay: bc f2[64][44]=22528 @33088, invd @55616
#define OFF_GS 0
#define OFF_A  33088
#define OFF_B  43328
#define OFF_MB 68928
#define OFF_BIS 49472
#define OFF_BC  33088
#define OFF_INVD 55616
#define SMEM_TOTAL 68960

__device__ __forceinline__ unsigned long long pack2(float a, float b) {
    unsigned long long r; asm("mov.b64 %0, {%1,%2};" : "=l"(r) : "f"(a), "f"(b)); return r;
}
__device__ __forceinline__ void fma2(unsigned long long& acc, unsigned long long a, unsigned long long b) {
    asm("fma.rn.f32x2 %0, %1, %2, %0;" : "+l"(acc) : "l"(a), "l"(b));
}
__device__ __forceinline__ void unpack2(unsigned long long x, float& lo, float& hi) {
    asm("mov.b64 {%0,%1}, %2;" : "=f"(lo), "=f"(hi) : "l"(x));
}
__device__ __forceinline__ unsigned f2bf(float x) {
    unsigned u = __float_as_uint(x);
    return (u + 0x7FFFu + ((u >> 16) & 1u)) >> 16;
}
__device__ __forceinline__ float bf2f(unsigned h) { return __uint_as_float(h << 16); }
__device__ __forceinline__ void mbar_init(unsigned m, unsigned c) {
    asm volatile("mbarrier.init.shared.b64 [%0], %1;" :: "r"(m), "r"(c) : "memory");
}
__device__ __forceinline__ void mbar_expect(unsigned m, unsigned b) {
    asm volatile("mbarrier.arrive.expect_tx.shared.b64 _, [%0], %1;" :: "r"(m), "r"(b) : "memory");
}
__device__ __forceinline__ void bulk_g2s(unsigned d, const void* s, unsigned b, unsigned m) {
    asm volatile("cp.async.bulk.shared::cluster.global.mbarrier::complete_tx::bytes [%0], [%1], %2, [%3];"
                 :: "r"(d), "l"(s), "r"(b), "r"(m) : "memory");
}
__device__ __forceinline__ void mbar_wait(unsigned m, unsigned p) {
    asm volatile(
        "{\n\t.reg .pred P1;\n\tWL_%=:\n\t"
        "mbarrier.try_wait.parity.acquire.cta.shared::cta.b64 P1, [%0], %1, 0x989680;\n\t"
        "@P1 bra.uni WD_%=;\n\tbra.uni WL_%=;\n\tWD_%=:\n\t}"
        :: "r"(m), "r"(p) : "memory");
}
__device__ __forceinline__ void ldsm4(unsigned* r, unsigned addr) {
    asm volatile("ldmatrix.sync.aligned.m8n8.x4.shared.b16 {%0,%1,%2,%3}, [%4];"
                 : "=r"(r[0]), "=r"(r[1]), "=r"(r[2]), "=r"(r[3]) : "r"(addr));
}
__device__ __forceinline__ void mma16816(float* d, const unsigned* a, unsigned b0, unsigned b1) {
    asm volatile("mma.sync.aligned.m16n8k16.row.col.f32.bf16.bf16.f32 "
                 "{%0,%1,%2,%3}, {%4,%5,%6,%7}, {%8,%9}, {%0,%1,%2,%3};"
                 : "+f"(d[0]), "+f"(d[1]), "+f"(d[2]), "+f"(d[3])
                 : "r"(a[0]), "r"(a[1]), "r"(a[2]), "r"(a[3]), "r"(b0), "r"(b1));
}

extern __shared__ char sm_[];

__global__ void __launch_bounds__(256) prep(
    const float* __restrict__ bmr, const float* __restrict__ bmi,
    const float* __restrict__ pr,  const float* __restrict__ pi)
{
    int t = blockIdx.x * 256 + threadIdx.x;
    if (t < 20480) {
        int f = t / 40, k = t % 40;
        int ch = f >> 5, fc = f & 31;
        float vals[2] = {bmr[t], bmi[t]};
        #pragma unroll
        for (int e2 = 0; e2 < 2; e2++) {
            int n = 2 * k + e2;
            unsigned h = f2bf(vals[e2]);
            unsigned l = f2bf(vals[e2] - bf2f(h));
            g_bmb[ch * 6400 + n * 40 + fc] = (unsigned short)h;
            g_bmb[ch * 6400 + 3200 + n * 40 + fc] = (unsigned short)l;
        }
    } else {
        int i = t - 20480;
        if (i < 4096) {
            int p = i >> 6, c = i & 63;
            g_ct[c * 64 + p] = make_float2(pr[i], pi[i]);
        }
    }
}

__global__ void __launch_bounds__(NTHR, 3) pv_main(
    const float* __restrict__ br, const float* __restrict__ bi)
{
    float*  brs = (float*)(sm_ + OFF_A);
    float*  bis = (float*)(sm_ + OFF_BIS);
    float2* gs  = (float2*)(sm_ + OFF_GS);
    unsigned sbase;
    asm("{ .reg .u64 t; cvta.to.shared.u64 t, %1; cvt.u32.u64 %0, t; }" : "=r"(sbase) : "l"(sm_));
    const unsigned mb_x = sbase + OFF_MB, mbB0 = sbase + OFF_MB + 8, mbB1 = sbase + OFF_MB + 16;

    const int tid  = threadIdx.x;
    const int tile = blockIdx.x;
    const int lane = tid & 31;
    const int w    = tid >> 5;

    if (tid == 0) {
        mbar_init(mb_x, 1); mbar_init(mbB0, 1); mbar_init(mbB1, 1);
        asm volatile("fence.proxy.async.shared::cta;" ::: "memory");
    }
    __syncthreads();
    if (tid == 0) {
        mbar_expect(mb_x, 32768);
        bulk_g2s(sbase + OFF_A, br + (size_t)tile * 4096, 16384, mb_x);
        bulk_g2s(sbase + OFF_BIS, bi + (size_t)tile * 4096, 16384, mb_x);
    }
    mbar_wait(mb_x, 0);

    // step 1: (|x|^2, rsqrt)
    #pragma unroll
    for (int r = 0; r < 16; r++) {
        int t = tid + r * NTHR;
        int c = t >> 9, f = t & 511;
        float re = brs[t], im = bis[t];
        float n = re * re + im * im;
        gs[c * 517 + f] = make_float2(n, rsqrtf(fmaxf(n, 1e-37f)));
    }
    __syncthreads();
    // step 2: trace-normalised amplitude
    #pragma unroll
    for (int r = 0; r < 2; r++) {
        int f = tid + r * NTHR;
        float tr = 0.f;
        #pragma unroll
        for (int c = 0; c < 8; c++) tr += gs[c * 517 + f].x;
        float sit = rsqrtf(fmaxf(tr, 1e-20f));
        #pragma unroll
        for (int c = 0; c < 8; c++) {
            float2 v = gs[c * 517 + f];
            gs[c * 517 + f].x = v.x * v.y * sit;
        }
    }
    __syncthreads();
    // step 3: g vectors
    float2 gv[16];
    #pragma unroll
    for (int r = 0; r < 16; r++) {
        int t = tid + r * NTHR;
        int c = t >> 9, f = t & 511;
        int fm = min(max(f - 1, 0), 509), fp = fm + 2;
        float a  = gs[c * 517 + f].x;
        float rm = gs[c * 517 + fm].y, rp = gs[c * 517 + fp].y;
        float xmr = brs[c * 512 + fm], xmi = bis[c * 512 + fm];
        float xpr = brs[c * 512 + fp], xpi = bis[c * 512 + fp];
        float s = a * rm * rp;
        gv[r] = make_float2(s * (xmr * xpr + xmi * xpi), s * (xmr * xpi - xmi * xpr));
    }
    __syncthreads();
    #pragma unroll
    for (int r = 0; r < 16; r++) {
        int t = tid + r * NTHR;
        gs[(t >> 9) * 517 + (t & 511)] = gv[r];
    }
    __syncthreads();   // brs/bis dead -> A/B regions free
    if (tid == 0) {    // prefetch B chunks 0 and 1
        mbar_expect(mbB0, 12800);
        bulk_g2s(sbase + OFF_B, (const char*)g_bmb, 12800, mbB0);
        mbar_expect(mbB1, 12800);
        bulk_g2s(sbase + OFF_B + 12800, (const char*)g_bmb + 12800, 12800, mbB1);
    }

    const unsigned e = PAIR_TBL[lane];
    const int iCh = e & 255, jCh = (e >> 8) & 255;
    const bool dg = (e & 0x10000u) != 0;

    const int mt = w & 3, nh = w >> 2;
    const unsigned arow = (unsigned)((mt * 16 + (lane & 7) + 8 * ((lane >> 3) & 1)) * 80
                                     + (lane >> 4) * 16);
    const unsigned brow = (unsigned)(((nh * 40) + (lane & 7)) * 80 + ((lane >> 3) & 3) * 16);

    float d[5][4] = {{0.f}};

    #pragma unroll 1
    for (int ch = 0; ch < CHUNKS; ch++) {
        const int b = ch & 1;
        if (ch > 0) {
            __syncthreads();   // mma(ch-1) done everywhere: A buf free, B buf b^1 free
            if (tid == 0 && ch + 1 < CHUNKS) {
                unsigned mb = ((ch + 1) & 1) ? mbB1 : mbB0;
                mbar_expect(mb, 12800);
                bulk_g2s(sbase + OFF_B + ((ch + 1) & 1) * 12800,
                         (const char*)g_bmb + (size_t)(ch + 1) * 12800, 12800, mb);
            }
        }
        // produce A(ch)
        unsigned uh[4], ul[4], vh[4], vl[4];
        #pragma unroll
        for (int r = 0; r < 4; r++) {
            int f = ch * 32 + 4 * w + r;
            float2 gi = gs[iCh * 517 + f], gj = gs[jCh * 517 + f];
            float u, v;
            if (dg) { u = gi.x*gi.x + gi.y*gi.y;  v = gj.x*gj.x + gj.y*gj.y; }
            else    { u = gi.x*gj.x + gi.y*gj.y;  v = gi.y*gj.x - gi.x*gj.y; }
            uh[r] = f2bf(u); ul[r] = f2bf(u - bf2f(uh[r]));
            vh[r] = f2bf(v); vl[r] = f2bf(v - bf2f(vh[r]));
        }
        char* Ab = sm_ + OFF_A;
        *(uint2*)(Ab + lane * 80 + 8 * w)        = make_uint2(uh[0]|(uh[1]<<16), uh[2]|(uh[3]<<16));
        *(uint2*)(Ab + 5120 + lane * 80 + 8 * w) = make_uint2(ul[0]|(ul[1]<<16), ul[2]|(ul[3]<<16));
        *(uint2*)(Ab + 2560 + lane * 80 + 8 * w) = make_uint2(vh[0]|(vh[1]<<16), vh[2]|(vh[3]<<16));
        *(uint2*)(Ab + 7680 + lane * 80 + 8 * w) = make_uint2(vl[0]|(vl[1]<<16), vl[2]|(vl[3]<<16));
        __syncthreads();   // A(ch) visible
        mbar_wait(b ? mbB1 : mbB0, (ch >> 1) & 1);

        const unsigned Abs = sbase + OFF_A;
        const unsigned Bbs = sbase + OFF_B + b * 12800;
        unsigned ah0[4], ah1[4], al0[4], al1[4];
        ldsm4(ah0, Abs + arow);
        ldsm4(ah1, Abs + arow + 32);
        ldsm4(al0, Abs + 5120 + arow);
        ldsm4(al1, Abs + 5120 + arow + 32);
        #pragma unroll
        for (int j = 0; j < 5; j++) {
            unsigned bh[4], bl[4];
            ldsm4(bh, Bbs + brow + j * 640);
            ldsm4(bl, Bbs + 6400 + brow + j * 640);
            mma16816(d[j], ah0, bh[0], bh[1]);
            mma16816(d[j], al0, bh[0], bh[1]);
            mma16816(d[j], ah0, bl[0], bl[1]);
            mma16816(d[j], ah1, bh[2], bh[3]);
            mma16816(d[j], al1, bh[2], bh[3]);
            mma16816(d[j], ah1, bl[2], bl[3]);
        }
    }

    // ---- stage D fragments to smem (gs dead) ----
    __syncthreads();
    float* stg = (float*)sm_;   // [64][82]
    {
        const int g = lane >> 2, tig = lane & 3;
        #pragma unroll
        for (int j = 0; j < 5; j++) {
            int col = nh * 40 + j * 8 + 2 * tig;
            int row = mt * 16 + g;
            *(float2*)(stg + row * 82 + col)       = make_float2(d[j][0], d[j][1]);
            *(float2*)(stg + (row + 8) * 82 + col) = make_float2(d[j][2], d[j][3]);
        }
    }
    __syncthreads();

    // ---- recombine into bc[c2][44] (A/B regions dead) ----
    float2* bc = (float2*)(sm_ + OFF_BC);
    #pragma unroll
    for (int kk = 0; kk < 5; kk++) {
        int k = 5 * w + kk;
        float2 s13 = *(float2*)(stg + lane * 82 + 2 * k);
        float2 s42 = *(float2*)(stg + (lane + 32) * 82 + 2 * k);
        if (dg) {
            bc[(iCh * 9) * 44 + k] = s13;
            bc[(jCh * 9) * 44 + k] = s42;
        } else {
            bc[(iCh * 8 + jCh) * 44 + k] = make_float2(s13.x - s42.y, s13.y + s42.x);
            bc[(jCh * 8 + iCh) * 44 + k] = make_float2(s13.x + s42.y, s13.y - s42.x);
        }
    }
    __syncthreads();

    float* invd = (float*)(sm_ + OFF_INVD);
    if (tid < 40) {
        float s = 0.f;
        #pragma unroll
        for (int dd = 0; dd < 8; dd++) s += bc[(dd * 9) * 44 + tid].x;
        invd[tid] = 1.0f / fmaxf(s, 1e-20f);
    }
    float2* ct = (float2*)sm_;   // overlays stg (dead)
    #pragma unroll
    for (int r = 0; r < 16; r++) {
        int idx = tid + r * NTHR;
        ct[idx] = g_ct[idx];
    }
    __syncthreads();

    const unsigned long long* ctu = (const unsigned long long*)ct;
    const unsigned long long* bcu = (const unsigned long long*)bc;
    const int p  = tid & 63;
    const int kq = tid >> 6;
    unsigned long long acc[10] = {0,0,0,0,0,0,0,0,0,0};
    #pragma unroll 4
    for (int c = 0; c < 64; c++) {
        unsigned long long m = ctu[c * 64 + p];
        const unsigned long long* bp = bcu + c * 44 + 10 * kq;
        #pragma unroll
        for (int r = 0; r < 10; r++) fma2(acc[r], m, bp[r]);
    }
    float* zt = g_z + (size_t)tile * 2560;
    #pragma unroll
    for (int r = 0; r < 10; r++) {
        int k = 10 * kq + r;
        float lo, hi; unpack2(acc[r], lo, hi);
        zt[k * 64 + p] = (lo - hi) * invd[k];
    }
}

__global__ void __launch_bounds__(256) iir_pass1(const float* __restrict__ tau)
{
    int tid = blockIdx.x * 256 + threadIdx.x;
    int p = tid & 63, k = (tid >> 6) % 40, ch = (tid / 2560) & 15, b = tid / 40960;
    float a = tau[k], om = 1.0f - a;
    size_t base = ((size_t)b * 400 + ch * 25) * 2560 + k * 64 + p;
    float y = 0.f;
    #pragma unroll 5
    for (int i = 0; i < 25; i++)
        y = a * y + om * g_z[base + (size_t)i * 2560];
    g_cf[((b * 16 + ch) * 40 + k) * 64 + p] = y;
}

__global__ void __launch_bounds__(256) iir_pass2(const float* __restrict__ tau,
                                                 float* __restrict__ out)
{
    int tid = blockIdx.x * 256 + threadIdx.x;
    int p = tid & 63, k = (tid >> 6) % 40, ch = (tid / 2560) & 15, b = tid / 40960;
    float a = tau[k], om = 1.0f - a;
    float a2 = a * a, a4 = a2 * a2, a8 = a4 * a4, a16 = a8 * a8;
    float a25 = a16 * a8 * a;
    float cf[16];
    #pragma unroll
    for (int j = 0; j < 15; j++)
        cf[j] = (j < ch) ? g_cf[((b * 16 + j) * 40 + k) * 64 + p] : 0.f;
    float y = 0.f;
    #pragma unroll
    for (int j = 0; j < 15; j++)
        if (j < ch) y = cf[j] + a25 * y;
    size_t base = ((size_t)b * 400 + ch * 25) * 2560 + k * 64 + p;
    #pragma unroll 5
    for (int i = 0; i < 25; i++) {
        y = a * y + om * g_z[base + (size_t)i * 2560];
        out[base + (size_t)i * 2560] = y;
    }
}

extern "C" void kernel_launch(void* const* d_in, const int* in_sizes, int n_in,
                              void* d_out, int out_size)
{
    const float* br  = (const float*)d_in[0];
    const float* bi  = (const float*)d_in[1];
    const float* bmr = (const float*)d_in[2];
    const float* bmi = (const float*)d_in[3];
    const float* pr  = (const float*)d_in[4];
    const float* pi  = (const float*)d_in[5];
    const float* tau = (const float*)d_in[6];

    cudaFuncSetAttribute(pv_main, cudaFuncAttributeMaxDynamicSharedMemorySize, SMEM_TOTAL);

    prep<<<96, 256>>>(bmr, bmi, pr, pi);
    pv_main<<<TILES, NTHR, SMEM_TOTAL>>>(br, bi);
    iir_pass1<<<320, 256>>>(tau);
    iir_pass2<<<320, 256>>>(tau, (float*)d_out);
}

// round 14
// speedup vs baseline: 1.1704x; 1.1704x over previous
#include <cuda_runtime.h>
#include <cuda_fp16.h>

#define TILES 800
#define NTHR  256
#define CHUNKS 16

__device__ float g_z[2 * 400 * 40 * 64];
__device__ float g_cf[2 * 16 * 40 * 64];
// fp16-split B staging: [16 ch][2 split][80 n][40 (32 k + 8 pad)] f16 = 12800 B/chunk
__device__ __align__(16) unsigned short g_bmb[16 * 6400];
__device__ __align__(16) float2 g_ct[64 * 64];

__constant__ unsigned PAIR_TBL[32] = {
  0x0100,0x0200,0x0300,0x0400,0x0500,0x0600,0x0700,
  0x0201,0x0301,0x0401,0x0501,0x0601,0x0701,
  0x0302,0x0402,0x0502,0x0602,0x0702,
  0x0403,0x0503,0x0603,0x0703,
  0x0504,0x0604,0x0704,
  0x0605,0x0705,
  0x0706,
  0x10100,0x10302,0x10504,0x10706
};

// smem (68976 B -> 3 CTAs/SM):
// gs f2[8][517] 33088 @0    (epi: stg f32[64][82]=20992 @0, then ct f2[64][64] @0)
// A dbuf 2x5120 @33088      (per buf: u rows 0-31 @0, v rows 32-63 @2560; stride 80B)
// B dbuf 2x12800 @43328     (per buf: hi 6400 + lo 6400)
// mbars @68928: mb_x, mbB0, mbB1
// prologue overlay: brs f32[4096]@33088, bis f32[4096]@49472
// epilogue overlay: bc f2[64][44]=22528 @33088, invd @55616
#define OFF_GS 0
#define OFF_A  33088
#define OFF_B  43328
#define OFF_MB 68928
#define OFF_BIS 49472
#define OFF_BC  33088
#define OFF_INVD 55616
#define SMEM_TOTAL 68976

__device__ __forceinline__ unsigned long long pack2(float a, float b) {
    unsigned long long r; asm("mov.b64 %0, {%1,%2};" : "=l"(r) : "f"(a), "f"(b)); return r;
}
__device__ __forceinline__ void fma2(unsigned long long& acc, unsigned long long a, unsigned long long b) {
    asm("fma.rn.f32x2 %0, %1, %2, %0;" : "+l"(acc) : "l"(a), "l"(b));
}
__device__ __forceinline__ void unpack2(unsigned long long x, float& lo, float& hi) {
    asm("mov.b64 {%0,%1}, %2;" : "=f"(lo), "=f"(hi) : "l"(x));
}
__device__ __forceinline__ unsigned h2pack(float f1, float f0) {   // {f0 lo, f1 hi}
    unsigned r; asm("cvt.rn.f16x2.f32 %0, %1, %2;" : "=r"(r) : "f"(f1), "f"(f0)); return r;
}
__device__ __forceinline__ void mbar_init(unsigned m, unsigned c) {
    asm volatile("mbarrier.init.shared.b64 [%0], %1;" :: "r"(m), "r"(c) : "memory");
}
__device__ __forceinline__ void mbar_expect(unsigned m, unsigned b) {
    asm volatile("mbarrier.arrive.expect_tx.shared.b64 _, [%0], %1;" :: "r"(m), "r"(b) : "memory");
}
__device__ __forceinline__ void bulk_g2s(unsigned d, const void* s, unsigned b, unsigned m) {
    asm volatile("cp.async.bulk.shared::cluster.global.mbarrier::complete_tx::bytes [%0], [%1], %2, [%3];"
                 :: "r"(d), "l"(s), "r"(b), "r"(m) : "memory");
}
__device__ __forceinline__ void mbar_wait(unsigned m, unsigned p) {
    asm volatile(
        "{\n\t.reg .pred P1;\n\tWL_%=:\n\t"
        "mbarrier.try_wait.parity.acquire.cta.shared::cta.b64 P1, [%0], %1, 0x989680;\n\t"
        "@P1 bra.uni WD_%=;\n\tbra.uni WL_%=;\n\tWD_%=:\n\t}"
        :: "r"(m), "r"(p) : "memory");
}
__device__ __forceinline__ void ldsm4(unsigned* r, unsigned addr) {
    asm volatile("ldmatrix.sync.aligned.m8n8.x4.shared.b16 {%0,%1,%2,%3}, [%4];"
                 : "=r"(r[0]), "=r"(r[1]), "=r"(r[2]), "=r"(r[3]) : "r"(addr));
}
__device__ __forceinline__ void mmaf16(float* d, unsigned a0, unsigned a1, unsigned a2, unsigned a3,
                                       unsigned b0, unsigned b1) {
    asm volatile("mma.sync.aligned.m16n8k16.row.col.f32.f16.f16.f32 "
                 "{%0,%1,%2,%3}, {%4,%5,%6,%7}, {%8,%9}, {%0,%1,%2,%3};"
                 : "+f"(d[0]), "+f"(d[1]), "+f"(d[2]), "+f"(d[3])
                 : "r"(a0), "r"(a1), "r"(a2), "r"(a3), "r"(b0), "r"(b1));
}

extern __shared__ char sm_[];

// ---- prep: fp16-split B staging + transposed c2p ----
__global__ void __launch_bounds__(256) prep(
    const float* __restrict__ bmr, const float* __restrict__ bmi,
    const float* __restrict__ pr,  const float* __restrict__ pi)
{
    int t = blockIdx.x * 256 + threadIdx.x;
    if (t < 20480) {
        int f = t / 40, k = t % 40;
        int ch = f >> 5, fc = f & 31;
        float vals[2] = {bmr[t], bmi[t]};
        #pragma unroll
        for (int e2 = 0; e2 < 2; e2++) {
            int n = 2 * k + e2;
            __half h = __float2half_rn(vals[e2]);
            __half l = __float2half_rn(vals[e2] - __half2float(h));
            g_bmb[ch * 6400 + n * 40 + fc] = __half_as_ushort(h);
            g_bmb[ch * 6400 + 3200 + n * 40 + fc] = __half_as_ushort(l);
        }
    } else {
        int i = t - 20480;
        if (i < 4096) {
            int p = i >> 6, c = i & 63;
            g_ct[c * 64 + p] = make_float2(pr[i], pi[i]);
        }
    }
}

__global__ void __launch_bounds__(NTHR, 3) pv_main(
    const float* __restrict__ br, const float* __restrict__ bi)
{
    float*  brs = (float*)(sm_ + OFF_A);
    float*  bis = (float*)(sm_ + OFF_BIS);
    float2* gs  = (float2*)(sm_ + OFF_GS);
    unsigned sbase;
    asm("{ .reg .u64 t; cvta.to.shared.u64 t, %1; cvt.u32.u64 %0, t; }" : "=r"(sbase) : "l"(sm_));
    const unsigned mb_x = sbase + OFF_MB, mbB0 = sbase + OFF_MB + 8, mbB1 = sbase + OFF_MB + 16;

    const int tid  = threadIdx.x;
    const int tile = blockIdx.x;
    const int lane = tid & 31;
    const int w    = tid >> 5;

    if (tid == 0) {
        mbar_init(mb_x, 1); mbar_init(mbB0, 1); mbar_init(mbB1, 1);
        asm volatile("fence.proxy.async.shared::cta;" ::: "memory");
    }
    __syncthreads();
    if (tid == 0) {
        mbar_expect(mb_x, 32768);
        bulk_g2s(sbase + OFF_A, br + (size_t)tile * 4096, 16384, mb_x);
        bulk_g2s(sbase + OFF_BIS, bi + (size_t)tile * 4096, 16384, mb_x);
    }
    mbar_wait(mb_x, 0);

    // step 1: (|x|^2, rsqrt)
    #pragma unroll
    for (int r = 0; r < 16; r++) {
        int t = tid + r * NTHR;
        int c = t >> 9, f = t & 511;
        float re = brs[t], im = bis[t];
        float n = re * re + im * im;
        gs[c * 517 + f] = make_float2(n, rsqrtf(fmaxf(n, 1e-37f)));
    }
    __syncthreads();
    // step 2: trace-normalised amplitude
    #pragma unroll
    for (int r = 0; r < 2; r++) {
        int f = tid + r * NTHR;
        float tr = 0.f;
        #pragma unroll
        for (int c = 0; c < 8; c++) tr += gs[c * 517 + f].x;
        float sit = rsqrtf(fmaxf(tr, 1e-20f));
        #pragma unroll
        for (int c = 0; c < 8; c++) {
            float2 v = gs[c * 517 + f];
            gs[c * 517 + f].x = v.x * v.y * sit;
        }
    }
    __syncthreads();
    // step 3: g vectors
    float2 gv[16];
    #pragma unroll
    for (int r = 0; r < 16; r++) {
        int t = tid + r * NTHR;
        int c = t >> 9, f = t & 511;
        int fm = min(max(f - 1, 0), 509), fp = fm + 2;
        float a  = gs[c * 517 + f].x;
        float rm = gs[c * 517 + fm].y, rp = gs[c * 517 + fp].y;
        float xmr = brs[c * 512 + fm], xmi = bis[c * 512 + fm];
        float xpr = brs[c * 512 + fp], xpi = bis[c * 512 + fp];
        float s = a * rm * rp;
        gv[r] = make_float2(s * (xmr * xpr + xmi * xpi), s * (xmr * xpi - xmi * xpr));
    }
    __syncthreads();
    #pragma unroll
    for (int r = 0; r < 16; r++) {
        int t = tid + r * NTHR;
        gs[(t >> 9) * 517 + (t & 511)] = gv[r];
    }
    __syncthreads();   // brs/bis dead -> A/B regions free
    if (tid == 0) {    // prefetch B chunks 0 and 1 (slots 0 and 1)
        mbar_expect(mbB0, 12800);
        bulk_g2s(sbase + OFF_B, (const char*)g_bmb, 12800, mbB0);
        mbar_expect(mbB1, 12800);
        bulk_g2s(sbase + OFF_B + 12800, (const char*)g_bmb + 12800, 12800, mbB1);
    }

    const unsigned e = PAIR_TBL[lane];
    const int iCh = e & 255, jCh = (e >> 8) & 255;
    const bool dg = (e & 0x10000u) != 0;

    const int mt = w & 3, nh = w >> 2;
    const unsigned arow = (unsigned)((mt * 16 + (lane & 7) + 8 * ((lane >> 3) & 1)) * 80
                                     + (lane >> 4) * 16);
    const unsigned brow = (unsigned)(((nh * 40) + (lane & 7)) * 80 + ((lane >> 3) & 3) * 16);

    float d[5][4] = {{0.f}};

    #pragma unroll 1
    for (int ch = 0; ch < CHUNKS; ch++) {
        const int b = ch & 1;
        // produce A(ch): fp16, rows lane (u) and lane+32 (v), cols 4w..4w+3
        float u[4], v[4];
        #pragma unroll
        for (int r = 0; r < 4; r++) {
            int f = ch * 32 + 4 * w + r;
            float2 gi = gs[iCh * 517 + f], gj = gs[jCh * 517 + f];
            if (dg) { u[r] = gi.x*gi.x + gi.y*gi.y;  v[r] = gj.x*gj.x + gj.y*gj.y; }
            else    { u[r] = gi.x*gj.x + gi.y*gj.y;  v[r] = gi.y*gj.x - gi.x*gj.y; }
        }
        char* Ab = sm_ + OFF_A + b * 5120;
        *(uint2*)(Ab + lane * 80 + 8 * w)        = make_uint2(h2pack(u[1], u[0]), h2pack(u[3], u[2]));
        *(uint2*)(Ab + 2560 + lane * 80 + 8 * w) = make_uint2(h2pack(v[1], v[0]), h2pack(v[3], v[2]));
        __syncthreads();   // A(ch) visible; mma(ch-1) done by all -> B slot b^1 free

        // R12-proven protocol: only re-issue from ch>=1 (chunks 0,1 prefetched pre-loop)
        if (tid == 0 && ch >= 1 && ch + 1 < CHUNKS) {
            unsigned mb = ((ch + 1) & 1) ? mbB1 : mbB0;
            mbar_expect(mb, 12800);
            bulk_g2s(sbase + OFF_B + ((ch + 1) & 1) * 12800,
                     (const char*)g_bmb + (size_t)(ch + 1) * 12800, 12800, mb);
        }
        mbar_wait(b ? mbB1 : mbB0, (ch >> 1) & 1);

        const unsigned Abs = sbase + OFF_A + b * 5120;
        const unsigned Bbs = sbase + OFF_B + b * 12800;
        unsigned ah0[4], ah1[4];
        ldsm4(ah0, Abs + arow);          // A, k0-15
        ldsm4(ah1, Abs + arow + 32);     // A, k16-31
        #pragma unroll
        for (int j = 0; j < 5; j++) {
            unsigned bh[4], bl[4];
            ldsm4(bh, Bbs + brow + j * 640);          // B hi
            ldsm4(bl, Bbs + 6400 + brow + j * 640);   // B lo
            mmaf16(d[j], ah0[0], ah0[1], ah0[2], ah0[3], bh[0], bh[1]);
            mmaf16(d[j], ah1[0], ah1[1], ah1[2], ah1[3], bh[2], bh[3]);
            mmaf16(d[j], ah0[0], ah0[1], ah0[2], ah0[3], bl[0], bl[1]);
            mmaf16(d[j], ah1[0], ah1[1], ah1[2], ah1[3], bl[2], bl[3]);
        }
    }

    // ---- stage D fragments to smem (gs dead) ----
    __syncthreads();
    float* stg = (float*)sm_;   // [64][82]
    {
        const int g = lane >> 2, tig = lane & 3;
        #pragma unroll
        for (int j = 0; j < 5; j++) {
            int col = nh * 40 + j * 8 + 2 * tig;
            int row = mt * 16 + g;
            *(float2*)(stg + row * 82 + col)       = make_float2(d[j][0], d[j][1]);
            *(float2*)(stg + (row + 8) * 82 + col) = make_float2(d[j][2], d[j][3]);
        }
    }
    __syncthreads();

    // ---- recombine into bc[c2][44] (A/B regions dead) ----
    float2* bc = (float2*)(sm_ + OFF_BC);
    #pragma unroll
    for (int kk = 0; kk < 5; kk++) {
        int k = 5 * w + kk;
        float2 s13 = *(float2*)(stg + lane * 82 + 2 * k);
        float2 s42 = *(float2*)(stg + (lane + 32) * 82 + 2 * k);
        if (dg) {
            bc[(iCh * 9) * 44 + k] = s13;
            bc[(jCh * 9) * 44 + k] = s42;
        } else {
            bc[(iCh * 8 + jCh) * 44 + k] = make_float2(s13.x - s42.y, s13.y + s42.x);
            bc[(jCh * 8 + iCh) * 44 + k] = make_float2(s13.x + s42.y, s13.y - s42.x);
        }
    }
    __syncthreads();

    float* invd = (float*)(sm_ + OFF_INVD);
    if (tid < 40) {
        float s = 0.f;
        #pragma unroll
        for (int dd = 0; dd < 8; dd++) s += bc[(dd * 9) * 44 + tid].x;
        invd[tid] = 1.0f / fmaxf(s, 1e-20f);
    }
    float2* ct = (float2*)sm_;   // overlays stg (dead)
    #pragma unroll
    for (int r = 0; r < 16; r++) {
        int idx = tid + r * NTHR;
        ct[idx] = g_ct[idx];
    }
    __syncthreads();

    const unsigned long long* ctu = (const unsigned long long*)ct;
    const unsigned long long* bcu = (const unsigned long long*)bc;
    const int p  = tid & 63;
    const int kq = tid >> 6;
    unsigned long long acc[10] = {0,0,0,0,0,0,0,0,0,0};
    #pragma unroll 4
    for (int c = 0; c < 64; c++) {
        unsigned long long m = ctu[c * 64 + p];
        const unsigned long long* bp = bcu + c * 44 + 10 * kq;
        #pragma unroll
        for (int r = 0; r < 10; r++) fma2(acc[r], m, bp[r]);
    }
    float* zt = g_z + (size_t)tile * 2560;
    #pragma unroll
    for (int r = 0; r < 10; r++) {
        int k = 10 * kq + r;
        float lo, hi; unpack2(acc[r], lo, hi);
        zt[k * 64 + p] = (lo - hi) * invd[k];
    }
}

__global__ void __launch_bounds__(256) iir_pass1(const float* __restrict__ tau)
{
    int tid = blockIdx.x * 256 + threadIdx.x;
    int p = tid & 63, k = (tid >> 6) % 40, ch = (tid / 2560) & 15, b = tid / 40960;
    float a = tau[k], om = 1.0f - a;
    size_t base = ((size_t)b * 400 + ch * 25) * 2560 + k * 64 + p;
    float x[25];
    #pragma unroll
    for (int i = 0; i < 25; i++)
        x[i] = g_z[base + (size_t)i * 2560];
    float y = 0.f;
    #pragma unroll
    for (int i = 0; i < 25; i++)
        y = a * y + om * x[i];
    g_cf[((b * 16 + ch) * 40 + k) * 64 + p] = y;
}

__global__ void __launch_bounds__(256) iir_pass2(const float* __restrict__ tau,
                                                 float* __restrict__ out)
{
    int tid = blockIdx.x * 256 + threadIdx.x;
    int p = tid & 63, k = (tid >> 6) % 40, ch = (tid / 2560) & 15, b = tid / 40960;
    float a = tau[k], om = 1.0f - a;
    float a2 = a * a, a4 = a2 * a2, a8 = a4 * a4, a16 = a8 * a8;
    float a25 = a16 * a8 * a;
    float cf[16];
    #pragma unroll
    for (int j = 0; j < 15; j++)
        cf[j] = (j < ch) ? g_cf[((b * 16 + j) * 40 + k) * 64 + p] : 0.f;
    float y = 0.f;
    #pragma unroll
    for (int j = 0; j < 15; j++)
        if (j < ch) y = cf[j] + a25 * y;
    size_t base = ((size_t)b * 400 + ch * 25) * 2560 + k * 64 + p;
    float x[25];
    #pragma unroll
    for (int i = 0; i < 25; i++)
        x[i] = g_z[base + (size_t)i * 2560];
    #pragma unroll
    for (int i = 0; i < 25; i++) {
        y = a * y + om * x[i];
        out[base + (size_t)i * 2560] = y;
    }
}

extern "C" void kernel_launch(void* const* d_in, const int* in_sizes, int n_in,
                              void* d_out, int out_size)
{
    const float* br  = (const float*)d_in[0];
    const float* bi  = (const float*)d_in[1];
    const float* bmr = (const float*)d_in[2];
    const float* bmi = (const float*)d_in[3];
    const float* pr  = (const float*)d_in[4];
    const float* pi  = (const float*)d_in[5];
    const float* tau = (const float*)d_in[6];

    cudaFuncSetAttribute(pv_main, cudaFuncAttributeMaxDynamicSharedMemorySize, SMEM_TOTAL);

    prep<<<96, 256>>>(bmr, bmi, pr, pi);
    pv_main<<<TILES, NTHR, SMEM_TOTAL>>>(br, bi);
    iir_pass1<<<320, 256>>>(tau);
    iir_pass2<<<320, 256>>>(tau, (float*)d_out);
}

// round 15
// speedup vs baseline: 1.3360x; 1.1415x over previous
#include <cuda_runtime.h>
#include <cuda_fp16.h>

#define TILES 800
#define NTHR  256
#define CHUNKS 16

__device__ float g_z[2 * 400 * 40 * 64];
__device__ float g_cf[2 * 25 * 40 * 64];
// fp16 B staging: [16 ch][80 n][40 (32 k + 8 pad)] f16 = 6400 B/chunk
__device__ __align__(16) unsigned short g_bmb[16 * 3200];
__device__ __align__(16) float2 g_ct[64 * 64];

__constant__ unsigned PAIR_TBL[32] = {
  0x0100,0x0200,0x0300,0x0400,0x0500,0x0600,0x0700,
  0x0201,0x0301,0x0401,0x0501,0x0601,0x0701,
  0x0302,0x0402,0x0502,0x0602,0x0702,
  0x0403,0x0503,0x0603,0x0703,
  0x0504,0x0604,0x0704,
  0x0605,0x0705,
  0x0706,
  0x10100,0x10302,0x10504,0x10706
};

// smem (65888 B -> 3 CTAs/SM):
// gs f2[8][517] 33088 @0    (epi: stg f32[64][82]=20992 @0, then ct f2[64][64] @0)
// A dbuf 2x5120 @33088      (per buf: u rows 0-31 @0, v rows 32-63 @2560; stride 80B)
// B dbuf 2x6400 @43328      (fp16 hi only)
// prologue overlay: brs f32[4096]@33088, bis f32[4096]@49472 (ends 65856)
// epilogue overlay: bc f2[64][44]=22528 @33088, invd @55616
// mbars @65856: mb_x, mbB0, mbB1
#define OFF_GS 0
#define OFF_A  33088
#define OFF_B  43328
#define OFF_BIS 49472
#define OFF_BC  33088
#define OFF_INVD 55616
#define OFF_MB 65856
#define SMEM_TOTAL 65888

__device__ __forceinline__ unsigned long long pack2(float a, float b) {
    unsigned long long r; asm("mov.b64 %0, {%1,%2};" : "=l"(r) : "f"(a), "f"(b)); return r;
}
__device__ __forceinline__ void fma2(unsigned long long& acc, unsigned long long a, unsigned long long b) {
    asm("fma.rn.f32x2 %0, %1, %2, %0;" : "+l"(acc) : "l"(a), "l"(b));
}
__device__ __forceinline__ void unpack2(unsigned long long x, float& lo, float& hi) {
    asm("mov.b64 {%0,%1}, %2;" : "=f"(lo), "=f"(hi) : "l"(x));
}
__device__ __forceinline__ unsigned h2pack(float f1, float f0) {   // {f0 lo, f1 hi}
    unsigned r; asm("cvt.rn.f16x2.f32 %0, %1, %2;" : "=r"(r) : "f"(f1), "f"(f0)); return r;
}
__device__ __forceinline__ void mbar_init(unsigned m, unsigned c) {
    asm volatile("mbarrier.init.shared.b64 [%0], %1;" :: "r"(m), "r"(c) : "memory");
}
__device__ __forceinline__ void mbar_expect(unsigned m, unsigned b) {
    asm volatile("mbarrier.arrive.expect_tx.shared.b64 _, [%0], %1;" :: "r"(m), "r"(b) : "memory");
}
__device__ __forceinline__ void bulk_g2s(unsigned d, const void* s, unsigned b, unsigned m) {
    asm volatile("cp.async.bulk.shared::cluster.global.mbarrier::complete_tx::bytes [%0], [%1], %2, [%3];"
                 :: "r"(d), "l"(s), "r"(b), "r"(m) : "memory");
}
__device__ __forceinline__ void mbar_wait(unsigned m, unsigned p) {
    asm volatile(
        "{\n\t.reg .pred P1;\n\tWL_%=:\n\t"
        "mbarrier.try_wait.parity.acquire.cta.shared::cta.b64 P1, [%0], %1, 0x989680;\n\t"
        "@P1 bra.uni WD_%=;\n\tbra.uni WL_%=;\n\tWD_%=:\n\t}"
        :: "r"(m), "r"(p) : "memory");
}
__device__ __forceinline__ void ldsm4(unsigned* r, unsigned addr) {
    asm volatile("ldmatrix.sync.aligned.m8n8.x4.shared.b16 {%0,%1,%2,%3}, [%4];"
                 : "=r"(r[0]), "=r"(r[1]), "=r"(r[2]), "=r"(r[3]) : "r"(addr));
}
__device__ __forceinline__ void mmaf16(float* d, unsigned a0, unsigned a1, unsigned a2, unsigned a3,
                                       unsigned b0, unsigned b1) {
    asm volatile("mma.sync.aligned.m16n8k16.row.col.f32.f16.f16.f32 "
                 "{%0,%1,%2,%3}, {%4,%5,%6,%7}, {%8,%9}, {%0,%1,%2,%3};"
                 : "+f"(d[0]), "+f"(d[1]), "+f"(d[2]), "+f"(d[3])
                 : "r"(a0), "r"(a1), "r"(a2), "r"(a3), "r"(b0), "r"(b1));
}

extern __shared__ char sm_[];

// ---- prep: fp16 B staging + transposed c2p ----
__global__ void __launch_bounds__(256) prep(
    const float* __restrict__ bmr, const float* __restrict__ bmi,
    const float* __restrict__ pr,  const float* __restrict__ pi)
{
    int t = blockIdx.x * 256 + threadIdx.x;
    if (t < 20480) {
        int f = t / 40, k = t % 40;
        int ch = f >> 5, fc = f & 31;
        float vals[2] = {bmr[t], bmi[t]};
        #pragma unroll
        for (int e2 = 0; e2 < 2; e2++) {
            int n = 2 * k + e2;
            g_bmb[ch * 3200 + n * 40 + fc] =
                __half_as_ushort(__float2half_rn(vals[e2]));
        }
    } else {
        int i = t - 20480;
        if (i < 4096) {
            int p = i >> 6, c = i & 63;
            g_ct[c * 64 + p] = make_float2(pr[i], pi[i]);
        }
    }
}

__global__ void __launch_bounds__(NTHR, 3) pv_main(
    const float* __restrict__ br, const float* __restrict__ bi)
{
    float*  brs = (float*)(sm_ + OFF_A);
    float*  bis = (float*)(sm_ + OFF_BIS);
    float2* gs  = (float2*)(sm_ + OFF_GS);
    unsigned sbase;
    asm("{ .reg .u64 t; cvta.to.shared.u64 t, %1; cvt.u32.u64 %0, t; }" : "=r"(sbase) : "l"(sm_));
    const unsigned mb_x = sbase + OFF_MB, mbB0 = sbase + OFF_MB + 8, mbB1 = sbase + OFF_MB + 16;

    const int tid  = threadIdx.x;
    const int tile = blockIdx.x;
    const int lane = tid & 31;
    const int w    = tid >> 5;

    if (tid == 0) {
        mbar_init(mb_x, 1); mbar_init(mbB0, 1); mbar_init(mbB1, 1);
        asm volatile("fence.proxy.async.shared::cta;" ::: "memory");
    }
    __syncthreads();
    if (tid == 0) {
        mbar_expect(mb_x, 32768);
        bulk_g2s(sbase + OFF_A, br + (size_t)tile * 4096, 16384, mb_x);
        bulk_g2s(sbase + OFF_BIS, bi + (size_t)tile * 4096, 16384, mb_x);
    }
    mbar_wait(mb_x, 0);

    // step 1: (|x|^2, rsqrt)
    #pragma unroll
    for (int r = 0; r < 16; r++) {
        int t = tid + r * NTHR;
        int c = t >> 9, f = t & 511;
        float re = brs[t], im = bis[t];
        float n = re * re + im * im;
        gs[c * 517 + f] = make_float2(n, rsqrtf(fmaxf(n, 1e-37f)));
    }
    __syncthreads();
    // step 2: trace-normalised amplitude
    #pragma unroll
    for (int r = 0; r < 2; r++) {
        int f = tid + r * NTHR;
        float tr = 0.f;
        #pragma unroll
        for (int c = 0; c < 8; c++) tr += gs[c * 517 + f].x;
        float sit = rsqrtf(fmaxf(tr, 1e-20f));
        #pragma unroll
        for (int c = 0; c < 8; c++) {
            float2 v = gs[c * 517 + f];
            gs[c * 517 + f].x = v.x * v.y * sit;
        }
    }
    __syncthreads();
    // step 3: g vectors
    float2 gv[16];
    #pragma unroll
    for (int r = 0; r < 16; r++) {
        int t = tid + r * NTHR;
        int c = t >> 9, f = t & 511;
        int fm = min(max(f - 1, 0), 509), fp = fm + 2;
        float a  = gs[c * 517 + f].x;
        float rm = gs[c * 517 + fm].y, rp = gs[c * 517 + fp].y;
        float xmr = brs[c * 512 + fm], xmi = bis[c * 512 + fm];
        float xpr = brs[c * 512 + fp], xpi = bis[c * 512 + fp];
        float s = a * rm * rp;
        gv[r] = make_float2(s * (xmr * xpr + xmi * xpi), s * (xmr * xpi - xmi * xpr));
    }
    __syncthreads();
    #pragma unroll
    for (int r = 0; r < 16; r++) {
        int t = tid + r * NTHR;
        gs[(t >> 9) * 517 + (t & 511)] = gv[r];
    }
    __syncthreads();   // brs/bis dead -> A/B regions free
    if (tid == 0) {    // prefetch B chunks 0 and 1
        mbar_expect(mbB0, 6400);
        bulk_g2s(sbase + OFF_B, (const char*)g_bmb, 6400, mbB0);
        mbar_expect(mbB1, 6400);
        bulk_g2s(sbase + OFF_B + 6400, (const char*)g_bmb + 6400, 6400, mbB1);
    }

    const unsigned e = PAIR_TBL[lane];
    const int iCh = e & 255, jCh = (e >> 8) & 255;
    const bool dg = (e & 0x10000u) != 0;

    const int mt = w & 3, nh = w >> 2;
    const unsigned arow = (unsigned)((mt * 16 + (lane & 7) + 8 * ((lane >> 3) & 1)) * 80
                                     + (lane >> 4) * 16);
    const unsigned brow = (unsigned)(((nh * 40) + (lane & 7)) * 80 + ((lane >> 3) & 3) * 16);

    float d[5][4] = {{0.f}};

    #pragma unroll 1
    for (int ch = 0; ch < CHUNKS; ch++) {
        const int b = ch & 1;
        // produce A(ch): fp16, rows lane (u) and lane+32 (v), cols 4w..4w+3
        float u[4], v[4];
        #pragma unroll
        for (int r = 0; r < 4; r++) {
            int f = ch * 32 + 4 * w + r;
            float2 gi = gs[iCh * 517 + f], gj = gs[jCh * 517 + f];
            if (dg) { u[r] = gi.x*gi.x + gi.y*gi.y;  v[r] = gj.x*gj.x + gj.y*gj.y; }
            else    { u[r] = gi.x*gj.x + gi.y*gj.y;  v[r] = gi.y*gj.x - gi.x*gj.y; }
        }
        char* Ab = sm_ + OFF_A + b * 5120;
        *(uint2*)(Ab + lane * 80 + 8 * w)        = make_uint2(h2pack(u[1], u[0]), h2pack(u[3], u[2]));
        *(uint2*)(Ab + 2560 + lane * 80 + 8 * w) = make_uint2(h2pack(v[1], v[0]), h2pack(v[3], v[2]));
        __syncthreads();   // A(ch) visible; mma(ch-1) done by all -> B slot b^1 free

        if (tid == 0 && ch >= 1 && ch + 1 < CHUNKS) {
            unsigned mb = ((ch + 1) & 1) ? mbB1 : mbB0;
            mbar_expect(mb, 6400);
            bulk_g2s(sbase + OFF_B + ((ch + 1) & 1) * 6400,
                     (const char*)g_bmb + (size_t)(ch + 1) * 6400, 6400, mb);
        }
        mbar_wait(b ? mbB1 : mbB0, (ch >> 1) & 1);

        const unsigned Abs = sbase + OFF_A + b * 5120;
        const unsigned Bbs = sbase + OFF_B + b * 6400;
        unsigned ah0[4], ah1[4];
        ldsm4(ah0, Abs + arow);          // A, k0-15
        ldsm4(ah1, Abs + arow + 32);     // A, k16-31
        #pragma unroll
        for (int j = 0; j < 5; j++) {
            unsigned bh[4];
            ldsm4(bh, Bbs + brow + j * 640);
            mmaf16(d[j], ah0[0], ah0[1], ah0[2], ah0[3], bh[0], bh[1]);
            mmaf16(d[j], ah1[0], ah1[1], ah1[2], ah1[3], bh[2], bh[3]);
        }
    }

    // ---- stage D fragments to smem (gs dead) ----
    __syncthreads();
    float* stg = (float*)sm_;   // [64][82]
    {
        const int g = lane >> 2, tig = lane & 3;
        #pragma unroll
        for (int j = 0; j < 5; j++) {
            int col = nh * 40 + j * 8 + 2 * tig;
            int row = mt * 16 + g;
            *(float2*)(stg + row * 82 + col)       = make_float2(d[j][0], d[j][1]);
            *(float2*)(stg + (row + 8) * 82 + col) = make_float2(d[j][2], d[j][3]);
        }
    }
    __syncthreads();

    // ---- recombine into bc[c2][44] ----
    float2* bc = (float2*)(sm_ + OFF_BC);
    #pragma unroll
    for (int kk = 0; kk < 5; kk++) {
        int k = 5 * w + kk;
        float2 s13 = *(float2*)(stg + lane * 82 + 2 * k);
        float2 s42 = *(float2*)(stg + (lane + 32) * 82 + 2 * k);
        if (dg) {
            bc[(iCh * 9) * 44 + k] = s13;
            bc[(jCh * 9) * 44 + k] = s42;
        } else {
            bc[(iCh * 8 + jCh) * 44 + k] = make_float2(s13.x - s42.y, s13.y + s42.x);
            bc[(jCh * 8 + iCh) * 44 + k] = make_float2(s13.x + s42.y, s13.y - s42.x);
        }
    }
    __syncthreads();

    float* invd = (float*)(sm_ + OFF_INVD);
    if (tid < 40) {
        float s = 0.f;
        #pragma unroll
        for (int dd = 0; dd < 8; dd++) s += bc[(dd * 9) * 44 + tid].x;
        invd[tid] = 1.0f / fmaxf(s, 1e-20f);
    }
    float2* ct = (float2*)sm_;   // overlays stg (dead)
    #pragma unroll
    for (int r = 0; r < 16; r++) {
        int idx = tid + r * NTHR;
        ct[idx] = g_ct[idx];
    }
    __syncthreads();

    const unsigned long long* ctu = (const unsigned long long*)ct;
    const unsigned long long* bcu = (const unsigned long long*)bc;
    const int p  = tid & 63;
    const int kq = tid >> 6;
    unsigned long long acc[10] = {0,0,0,0,0,0,0,0,0,0};
    #pragma unroll 4
    for (int c = 0; c < 64; c++) {
        unsigned long long m = ctu[c * 64 + p];
        const unsigned long long* bp = bcu + c * 44 + 10 * kq;
        #pragma unroll
        for (int r = 0; r < 10; r++) fma2(acc[r], m, bp[r]);
    }
    float* zt = g_z + (size_t)tile * 2560;
    #pragma unroll
    for (int r = 0; r < 10; r++) {
        int k = 10 * kq + r;
        float lo, hi; unpack2(acc[r], lo, hi);
        zt[k * 64 + p] = (lo - hi) * invd[k];
    }
}

// ---- IIR: 25 chunks of 16 frames (500 blocks each pass) ----
__global__ void __launch_bounds__(256) iir_pass1(const float* __restrict__ tau)
{
    int tid = blockIdx.x * 256 + threadIdx.x;   // 128000 = B*25*K*P
    int p = tid & 63, k = (tid >> 6) % 40, ch = (tid / 2560) % 25, b = tid / 64000;
    float a = tau[k], om = 1.0f - a;
    size_t base = ((size_t)b * 400 + ch * 16) * 2560 + k * 64 + p;
    float x[16];
    #pragma unroll
    for (int i = 0; i < 16; i++)
        x[i] = g_z[base + (size_t)i * 2560];
    float y = 0.f;
    #pragma unroll
    for (int i = 0; i < 16; i++)
        y = a * y + om * x[i];
    g_cf[((b * 25 + ch) * 40 + k) * 64 + p] = y;
}

__global__ void __launch_bounds__(256) iir_pass2(const float* __restrict__ tau,
                                                 float* __restrict__ out)
{
    int tid = blockIdx.x * 256 + threadIdx.x;
    int p = tid & 63, k = (tid >> 6) % 40, ch = (tid / 2560) % 25, b = tid / 64000;
    float a = tau[k], om = 1.0f - a;
    float a2 = a * a, a4 = a2 * a2, a8 = a4 * a4;
    float a16 = a8 * a8;
    float cf[24];
    #pragma unroll
    for (int j = 0; j < 24; j++)
        cf[j] = (j < ch) ? g_cf[((b * 25 + j) * 40 + k) * 64 + p] : 0.f;
    float y = 0.f;
    #pragma unroll
    for (int j = 0; j < 24; j++)
        if (j < ch) y = cf[j] + a16 * y;
    size_t base = ((size_t)b * 400 + ch * 16) * 2560 + k * 64 + p;
    float x[16];
    #pragma unroll
    for (int i = 0; i < 16; i++)
        x[i] = g_z[base + (size_t)i * 2560];
    #pragma unroll
    for (int i = 0; i < 16; i++) {
        y = a * y + om * x[i];
        out[base + (size_t)i * 2560] = y;
    }
}

extern "C" void kernel_launch(void* const* d_in, const int* in_sizes, int n_in,
                              void* d_out, int out_size)
{
    const float* br  = (const float*)d_in[0];
    const float* bi  = (const float*)d_in[1];
    const float* bmr = (const float*)d_in[2];
    const float* bmi = (const float*)d_in[3];
    const float* pr  = (const float*)d_in[4];
    const float* pi  = (const float*)d_in[5];
    const float* tau = (const float*)d_in[6];

    cudaFuncSetAttribute(pv_main, cudaFuncAttributeMaxDynamicSharedMemorySize, SMEM_TOTAL);

    prep<<<96, 256>>>(bmr, bmi, pr, pi);
    pv_main<<<TILES, NTHR, SMEM_TOTAL>>>(br, bi);
    iir_pass1<<<500, 256>>>(tau);
    iir_pass2<<<500, 256>>>(tau, (float*)d_out);
}

// round 16
// speedup vs baseline: 1.4208x; 1.0635x over previous
#include <cuda_runtime.h>
#include <cuda_fp16.h>

#define TILES 800
#define NTHR  256
#define CHUNKS 8          // 64 f each

__device__ float g_z[2 * 400 * 40 * 64];
__device__ float g_cf[2 * 25 * 40 * 64];
// fp16 B staging: [8 ch][80 n][72 (64 k + 8 pad)] f16 = 11520 B/chunk
__device__ __align__(16) unsigned short g_bmb[8 * 5760];
__device__ __align__(16) float2 g_ct[64 * 64];

__constant__ unsigned PAIR_TBL[32] = {
  0x0100,0x0200,0x0300,0x0400,0x0500,0x0600,0x0700,
  0x0201,0x0301,0x0401,0x0501,0x0601,0x0701,
  0x0302,0x0402,0x0502,0x0602,0x0702,
  0x0403,0x0503,0x0603,0x0703,
  0x0504,0x0604,0x0704,
  0x0605,0x0705,
  0x0706,
  0x10100,0x10302,0x10504,0x10706
};

// smem (65888 B -> 3 CTAs/SM):
// gs f2[8][517] 33088 @0    (epi: stg f32[64][82]=20992 @0, then ct f2[64][64] @0)
// A single buf 9216 @33088  (u rows 0-31 @0, v rows 32-63 @4608; row stride 144B)
// B dbuf 2x11520 @42304 (ends 65344)
// prologue overlay: brs f32[4096]@33088, bis f32[4096]@49472 (ends 65856)
// epilogue overlay: bc f2[64][44]=22528 @33088, invd @55616
// mbars @65856: mb_x, mbB0, mbB1
#define OFF_GS 0
#define OFF_A  33088
#define OFF_B0 42304
#define OFF_B1 53824
#define OFF_BIS 49472
#define OFF_BC  33088
#define OFF_INVD 55616
#define OFF_MB 65856
#define SMEM_TOTAL 65888
#define B_BYTES 11520

__device__ __forceinline__ unsigned long long pack2(float a, float b) {
    unsigned long long r; asm("mov.b64 %0, {%1,%2};" : "=l"(r) : "f"(a), "f"(b)); return r;
}
__device__ __forceinline__ void fma2(unsigned long long& acc, unsigned long long a, unsigned long long b) {
    asm("fma.rn.f32x2 %0, %1, %2, %0;" : "+l"(acc) : "l"(a), "l"(b));
}
__device__ __forceinline__ void unpack2(unsigned long long x, float& lo, float& hi) {
    asm("mov.b64 {%0,%1}, %2;" : "=f"(lo), "=f"(hi) : "l"(x));
}
__device__ __forceinline__ unsigned h2pack(float f1, float f0) {   // {f0 lo, f1 hi}
    unsigned r; asm("cvt.rn.f16x2.f32 %0, %1, %2;" : "=r"(r) : "f"(f1), "f"(f0)); return r;
}
__device__ __forceinline__ void mbar_init(unsigned m, unsigned c) {
    asm volatile("mbarrier.init.shared.b64 [%0], %1;" :: "r"(m), "r"(c) : "memory");
}
__device__ __forceinline__ void mbar_expect(unsigned m, unsigned b) {
    asm volatile("mbarrier.arrive.expect_tx.shared.b64 _, [%0], %1;" :: "r"(m), "r"(b) : "memory");
}
__device__ __forceinline__ void bulk_g2s(unsigned d, const void* s, unsigned b, unsigned m) {
    asm volatile("cp.async.bulk.shared::cluster.global.mbarrier::complete_tx::bytes [%0], [%1], %2, [%3];"
                 :: "r"(d), "l"(s), "r"(b), "r"(m) : "memory");
}
__device__ __forceinline__ void mbar_wait(unsigned m, unsigned p) {
    asm volatile(
        "{\n\t.reg .pred P1;\n\tWL_%=:\n\t"
        "mbarrier.try_wait.parity.acquire.cta.shared::cta.b64 P1, [%0], %1, 0x989680;\n\t"
        "@P1 bra.uni WD_%=;\n\tbra.uni WL_%=;\n\tWD_%=:\n\t}"
        :: "r"(m), "r"(p) : "memory");
}
__device__ __forceinline__ void ldsm4(unsigned* r, unsigned addr) {
    asm volatile("ldmatrix.sync.aligned.m8n8.x4.shared.b16 {%0,%1,%2,%3}, [%4];"
                 : "=r"(r[0]), "=r"(r[1]), "=r"(r[2]), "=r"(r[3]) : "r"(addr));
}
__device__ __forceinline__ void mmaf16(float* d, unsigned a0, unsigned a1, unsigned a2, unsigned a3,
                                       unsigned b0, unsigned b1) {
    asm volatile("mma.sync.aligned.m16n8k16.row.col.f32.f16.f16.f32 "
                 "{%0,%1,%2,%3}, {%4,%5,%6,%7}, {%8,%9}, {%0,%1,%2,%3};"
                 : "+f"(d[0]), "+f"(d[1]), "+f"(d[2]), "+f"(d[3])
                 : "r"(a0), "r"(a1), "r"(a2), "r"(a3), "r"(b0), "r"(b1));
}

extern __shared__ char sm_[];

// ---- prep: fp16 B staging (64-f chunks, stride 72) + transposed c2p ----
__global__ void __launch_bounds__(256) prep(
    const float* __restrict__ bmr, const float* __restrict__ bmi,
    const float* __restrict__ pr,  const float* __restrict__ pi)
{
    int t = blockIdx.x * 256 + threadIdx.x;
    if (t < 20480) {
        int f = t / 40, k = t % 40;
        int ch = f >> 6, fc = f & 63;
        float vals[2] = {bmr[t], bmi[t]};
        #pragma unroll
        for (int e2 = 0; e2 < 2; e2++) {
            int n = 2 * k + e2;
            g_bmb[ch * 5760 + n * 72 + fc] =
                __half_as_ushort(__float2half_rn(vals[e2]));
        }
    } else {
        int i = t - 20480;
        if (i < 4096) {
            int p = i >> 6, c = i & 63;
            g_ct[c * 64 + p] = make_float2(pr[i], pi[i]);
        }
    }
}

__global__ void __launch_bounds__(NTHR, 3) pv_main(
    const float* __restrict__ br, const float* __restrict__ bi)
{
    float*  brs = (float*)(sm_ + OFF_A);
    float*  bis = (float*)(sm_ + OFF_BIS);
    float2* gs  = (float2*)(sm_ + OFF_GS);
    unsigned sbase;
    asm("{ .reg .u64 t; cvta.to.shared.u64 t, %1; cvt.u32.u64 %0, t; }" : "=r"(sbase) : "l"(sm_));
    const unsigned mb_x = sbase + OFF_MB, mbB0 = sbase + OFF_MB + 8, mbB1 = sbase + OFF_MB + 16;

    const int tid  = threadIdx.x;
    const int tile = blockIdx.x;
    const int lane = tid & 31;
    const int w    = tid >> 5;

    if (tid == 0) {
        mbar_init(mb_x, 1); mbar_init(mbB0, 1); mbar_init(mbB1, 1);
        asm volatile("fence.proxy.async.shared::cta;" ::: "memory");
    }
    __syncthreads();
    if (tid == 0) {
        mbar_expect(mb_x, 32768);
        bulk_g2s(sbase + OFF_A, br + (size_t)tile * 4096, 16384, mb_x);
        bulk_g2s(sbase + OFF_BIS, bi + (size_t)tile * 4096, 16384, mb_x);
    }
    mbar_wait(mb_x, 0);

    // merged step 1+2: per f: norms, trace, normalised amplitude + rsqrt
    #pragma unroll
    for (int r = 0; r < 2; r++) {
        int f = tid + r * NTHR;
        float n[8];
        float tr = 0.f;
        #pragma unroll
        for (int c = 0; c < 8; c++) {
            float re = brs[c * 512 + f], im = bis[c * 512 + f];
            n[c] = re * re + im * im;
            tr += n[c];
        }
        float sit = rsqrtf(fmaxf(tr, 1e-20f));
        #pragma unroll
        for (int c = 0; c < 8; c++) {
            float rn = rsqrtf(fmaxf(n[c], 1e-37f));
            gs[c * 517 + f] = make_float2(n[c] * rn * sit, rn);   // (|x|*sit, 1/|x|)
        }
    }
    __syncthreads();
    // step 3: g vectors
    float2 gv[16];
    #pragma unroll
    for (int r = 0; r < 16; r++) {
        int t = tid + r * NTHR;
        int c = t >> 9, f = t & 511;
        int fm = min(max(f - 1, 0), 509), fp = fm + 2;
        float a  = gs[c * 517 + f].x;
        float rm = gs[c * 517 + fm].y, rp = gs[c * 517 + fp].y;
        float xmr = brs[c * 512 + fm], xmi = bis[c * 512 + fm];
        float xpr = brs[c * 512 + fp], xpi = bis[c * 512 + fp];
        float s = a * rm * rp;
        gv[r] = make_float2(s * (xmr * xpr + xmi * xpi), s * (xmr * xpi - xmi * xpr));
    }
    __syncthreads();
    #pragma unroll
    for (int r = 0; r < 16; r++) {
        int t = tid + r * NTHR;
        gs[(t >> 9) * 517 + (t & 511)] = gv[r];
    }
    __syncthreads();   // brs/bis dead -> A/B regions free
    if (tid == 0) {    // prefetch B chunks 0 and 1
        mbar_expect(mbB0, B_BYTES);
        bulk_g2s(sbase + OFF_B0, (const char*)g_bmb, B_BYTES, mbB0);
        mbar_expect(mbB1, B_BYTES);
        bulk_g2s(sbase + OFF_B1, (const char*)g_bmb + B_BYTES, B_BYTES, mbB1);
    }

    const unsigned e = PAIR_TBL[lane];
    const int iCh = e & 255, jCh = (e >> 8) & 255;
    const bool dg = (e & 0x10000u) != 0;

    const int mt = w & 3, nh = w >> 2;
    const unsigned arow = (unsigned)((mt * 16 + (lane & 7) + 8 * ((lane >> 3) & 1)) * 144
                                     + (lane >> 4) * 16);
    const unsigned brow = (unsigned)(((nh * 40) + (lane & 7)) * 144 + ((lane >> 3) & 3) * 16);

    float d[5][4] = {{0.f}};

    #pragma unroll 1
    for (int ch = 0; ch < CHUNKS; ch++) {
        const int b = ch & 1;
        // produce A(ch): fp16, rows lane (u) / lane+32 (v), k-cols 8w..8w+7
        float u[8], v[8];
        #pragma unroll
        for (int r = 0; r < 8; r++) {
            int f = ch * 64 + 8 * w + r;
            float2 gi = gs[iCh * 517 + f], gj = gs[jCh * 517 + f];
            if (dg) { u[r] = gi.x*gi.x + gi.y*gi.y;  v[r] = gj.x*gj.x + gj.y*gj.y; }
            else    { u[r] = gi.x*gj.x + gi.y*gj.y;  v[r] = gi.y*gj.x - gi.x*gj.y; }
        }
        char* Ab = sm_ + OFF_A;
        *(uint4*)(Ab + lane * 144 + 16 * w) =
            make_uint4(h2pack(u[1], u[0]), h2pack(u[3], u[2]), h2pack(u[5], u[4]), h2pack(u[7], u[6]));
        *(uint4*)(Ab + 4608 + lane * 144 + 16 * w) =
            make_uint4(h2pack(v[1], v[0]), h2pack(v[3], v[2]), h2pack(v[5], v[4]), h2pack(v[7], v[6]));
        __syncthreads();   // A(ch) visible; mma(ch-1) done -> B slot b^1 free

        if (tid == 0 && ch >= 1 && ch + 1 < CHUNKS) {
            unsigned mb = ((ch + 1) & 1) ? mbB1 : mbB0;
            mbar_expect(mb, B_BYTES);
            bulk_g2s(sbase + (((ch + 1) & 1) ? OFF_B1 : OFF_B0),
                     (const char*)g_bmb + (size_t)(ch + 1) * B_BYTES, B_BYTES, mb);
        }
        mbar_wait(b ? mbB1 : mbB0, (ch >> 1) & 1);

        const unsigned Abs = sbase + OFF_A;
        const unsigned Bbs = sbase + (b ? OFF_B1 : OFF_B0);
        unsigned a0[4], a1[4], a2[4], a3[4];
        ldsm4(a0, Abs + arow);          // k0-15
        ldsm4(a1, Abs + arow + 32);     // k16-31
        ldsm4(a2, Abs + arow + 64);     // k32-47
        ldsm4(a3, Abs + arow + 96);     // k48-63
        #pragma unroll
        for (int j = 0; j < 5; j++) {
            unsigned b0[4], b1[4];
            ldsm4(b0, Bbs + brow + j * 1152);        // k0-31
            ldsm4(b1, Bbs + brow + j * 1152 + 64);   // k32-63
            mmaf16(d[j], a0[0], a0[1], a0[2], a0[3], b0[0], b0[1]);
            mmaf16(d[j], a1[0], a1[1], a1[2], a1[3], b0[2], b0[3]);
            mmaf16(d[j], a2[0], a2[1], a2[2], a2[3], b1[0], b1[1]);
            mmaf16(d[j], a3[0], a3[1], a3[2], a3[3], b1[2], b1[3]);
        }
        __syncthreads();   // mma(ch) done -> A buf free for ch+1
    }

    // ---- stage D fragments to smem (gs dead) ----
    float* stg = (float*)sm_;   // [64][82]
    {
        const int g = lane >> 2, tig = lane & 3;
        #pragma unroll
        for (int j = 0; j < 5; j++) {
            int col = nh * 40 + j * 8 + 2 * tig;
            int row = mt * 16 + g;
            *(float2*)(stg + row * 82 + col)       = make_float2(d[j][0], d[j][1]);
            *(float2*)(stg + (row + 8) * 82 + col) = make_float2(d[j][2], d[j][3]);
        }
    }
    __syncthreads();

    // ---- recombine into bc[c2][44] ----
    float2* bc = (float2*)(sm_ + OFF_BC);
    #pragma unroll
    for (int kk = 0; kk < 5; kk++) {
        int k = 5 * w + kk;
        float2 s13 = *(float2*)(stg + lane * 82 + 2 * k);
        float2 s42 = *(float2*)(stg + (lane + 32) * 82 + 2 * k);
        if (dg) {
            bc[(iCh * 9) * 44 + k] = s13;
            bc[(jCh * 9) * 44 + k] = s42;
        } else {
            bc[(iCh * 8 + jCh) * 44 + k] = make_float2(s13.x - s42.y, s13.y + s42.x);
            bc[(jCh * 8 + iCh) * 44 + k] = make_float2(s13.x + s42.y, s13.y - s42.x);
        }
    }
    __syncthreads();

    float* invd = (float*)(sm_ + OFF_INVD);
    if (tid < 40) {
        float s = 0.f;
        #pragma unroll
        for (int dd = 0; dd < 8; dd++) s += bc[(dd * 9) * 44 + tid].x;
        invd[tid] = 1.0f / fmaxf(s, 1e-20f);
    }
    float2* ct = (float2*)sm_;   // overlays stg (dead)
    #pragma unroll
    for (int r = 0; r < 16; r++) {
        int idx = tid + r * NTHR;
        ct[idx] = g_ct[idx];
    }
    __syncthreads();

    const unsigned long long* ctu = (const unsigned long long*)ct;
    const unsigned long long* bcu = (const unsigned long long*)bc;
    const int p  = tid & 63;
    const int kq = tid >> 6;
    unsigned long long acc[10] = {0,0,0,0,0,0,0,0,0,0};
    #pragma unroll 4
    for (int c = 0; c < 64; c++) {
        unsigned long long m = ctu[c * 64 + p];
        const unsigned long long* bp = bcu + c * 44 + 10 * kq;
        #pragma unroll
        for (int r = 0; r < 10; r++) fma2(acc[r], m, bp[r]);
    }
    float* zt = g_z + (size_t)tile * 2560;
    #pragma unroll
    for (int r = 0; r < 10; r++) {
        int k = 10 * kq + r;
        float lo, hi; unpack2(acc[r], lo, hi);
        zt[k * 64 + p] = (lo - hi) * invd[k];
    }
}

// ---- IIR: 25 chunks of 16 frames ----
__global__ void __launch_bounds__(256) iir_pass1(const float* __restrict__ tau)
{
    int tid = blockIdx.x * 256 + threadIdx.x;   // 64000 threads, float2 per thread
    int pp = (tid & 31) * 2;
    int k = (tid >> 5) % 40;
    int ch = (tid / 1280) % 25;
    int b = tid / 32000;
    float a = tau[k], om = 1.0f - a;
    size_t base = ((size_t)b * 400 + ch * 16) * 2560 + k * 64 + pp;
    float2 x[16];
    #pragma unroll
    for (int i = 0; i < 16; i++)
        x[i] = *(const float2*)(g_z + base + (size_t)i * 2560);
    float y0 = 0.f, y1 = 0.f;
    #pragma unroll
    for (int i = 0; i < 16; i++) {
        y0 = a * y0 + om * x[i].x;
        y1 = a * y1 + om * x[i].y;
    }
    *(float2*)(g_cf + ((b * 25 + ch) * 40 + k) * 64 + pp) = make_float2(y0, y1);
}

__global__ void __launch_bounds__(256) iir_pass2(const float* __restrict__ tau,
                                                 float* __restrict__ out)
{
    int tid = blockIdx.x * 256 + threadIdx.x;
    int p = tid & 63, k = (tid >> 6) % 40, ch = (tid / 2560) % 25, b = tid / 64000;
    float a = tau[k], om = 1.0f - a;
    float a2 = a * a, a4 = a2 * a2, a8 = a4 * a4;
    float a16 = a8 * a8;
    float cf[24];
    #pragma unroll
    for (int j = 0; j < 24; j++)
        cf[j] = (j < ch) ? g_cf[((b * 25 + j) * 40 + k) * 64 + p] : 0.f;
    float y = 0.f;
    #pragma unroll
    for (int j = 0; j < 24; j++)
        if (j < ch) y = cf[j] + a16 * y;
    size_t base = ((size_t)b * 400 + ch * 16) * 2560 + k * 64 + p;
    float x[16];
    #pragma unroll
    for (int i = 0; i < 16; i++)
        x[i] = g_z[base + (size_t)i * 2560];
    #pragma unroll
    for (int i = 0; i < 16; i++) {
        y = a * y + om * x[i];
        out[base + (size_t)i * 2560] = y;
    }
}

extern "C" void kernel_launch(void* const* d_in, const int* in_sizes, int n_in,
                              void* d_out, int out_size)
{
    const float* br  = (const float*)d_in[0];
    const float* bi  = (const float*)d_in[1];
    const float* bmr = (const float*)d_in[2];
    const float* bmi = (const float*)d_in[3];
    const float* pr  = (const float*)d_in[4];
    const float* pi  = (const float*)d_in[5];
    const float* tau = (const float*)d_in[6];

    cudaFuncSetAttribute(pv_main, cudaFuncAttributeMaxDynamicSharedMemorySize, SMEM_TOTAL);

    prep<<<96, 256>>>(bmr, bmi, pr, pi);
    pv_main<<<TILES, NTHR, SMEM_TOTAL>>>(br, bi);
    iir_pass1<<<250, 256>>>(tau);
    iir_pass2<<<500, 256>>>(tau, (float*)d_out);
}